// round 9
// baseline (speedup 1.0000x reference)
#include <cuda_runtime.h>
#include <cuda_bf16.h>
#include <cuda_fp16.h>
#include <cstdint>

// B=2,H=8 -> BH=16 heads; L=S=2048; D=64; fp32 in/out.
#define BH        16
#define Ls        2048
#define Dh        64
#define NT        128
#define NTILES    16
#define BROWS     32
#define NTHREADS  512
#define KSTR      72
#define VSTR      136

#define SDPA_TILEW      (128*KSTR + 64*VSTR)
#define SDPA_SMEM_BYTES ((SDPA_TILEW + 256 + 32) * 4)

#define AR_W            (128*KSTR)
#define ETILE_W         8704
#define ATTN_SMEM_BYTES ((4*AR_W + ETILE_W + 512) * 4)

// Exponent shift: stored values are exp(s/8 - ESH). Cancels in normalization.
// Keeps fp16 in range: max diag score/8 ~ 16 -> e^8 = 2981 << 65504.
#define ESH 8.0f

__device__ uint32_t g_Q [BH * Ls * 64];
__device__ uint32_t g_K [BH * Ls * 64];
__device__ uint32_t g_VT[BH * Dh * 2048];
__device__ __half g_EQh[(long)BH * Ls * Ls];
__device__ __half g_EKh[(long)BH * Ls * Ls];
__device__ float g_rpart[2 * BH * 16 * 2 * 128];
__device__ float g_cpart[2 * BH * 16 * 16 * 128];
__device__ float g_rsQ[BH * Ls];
__device__ float g_rsK[BH * Ls];

__global__ void convert_qk_kernel(const float* __restrict__ Q, const float* __restrict__ K)
{
    const unsigned NPAIR = BH * Ls * 32;
    unsigned i = blockIdx.x * 256 + threadIdx.x;
    const float2* src = (i < NPAIR) ? (const float2*)Q : (const float2*)K;
    uint32_t*     dst = (i < NPAIR) ? g_Q : g_K;
    unsigned p = (i < NPAIR) ? i : i - NPAIR;
    float2 v = src[p];
    __nv_bfloat16 hx = __float2bfloat16(v.x), hy = __float2bfloat16(v.y);
    __nv_bfloat162 hh; hh.x = hx; hh.y = hy;
    __nv_bfloat162 ll = __floats2bfloat162_rn(v.x - __bfloat162float(hx),
                                              v.y - __bfloat162float(hy));
    dst[2u*p]     = *reinterpret_cast<uint32_t*>(&hh);
    dst[2u*p + 1] = *reinterpret_cast<uint32_t*>(&ll);
}

__global__ void convert_v_kernel(const float* __restrict__ V)
{
    __shared__ float st[128][65];
    const int bh = blockIdx.x >> 4;
    const int j0 = (blockIdx.x & 15) * 128;
    const int tid = threadIdx.x;
    const float* vb = V + ((long)bh * Ls + j0) * Dh;
    for (int i = tid; i < 128 * 64; i += 256)
        st[i >> 6][i & 63] = vb[i];
    __syncthreads();
    for (int i = tid; i < 64 * 64; i += 256) {
        int d = i >> 6, jp = i & 63;
        float v0 = st[jp*2][d], v1 = st[jp*2 + 1][d];
        __half h0 = __float2half_rn(v0), h1 = __float2half_rn(v1);
        __half2 hh; hh.x = h0; hh.y = h1;
        __half2 ll; ll.x = __float2half_rn(v0 - __half2float(h0));
                    ll.y = __float2half_rn(v1 - __half2float(h1));
        long w = ((long)(bh * Dh + d) * 1024 + (j0 >> 1) + jp) * 2;
        g_VT[w]     = *reinterpret_cast<uint32_t*>(&hh);
        g_VT[w + 1] = *reinterpret_cast<uint32_t*>(&ll);
    }
}

__device__ __forceinline__ void mma_bf16(float* c, const uint32_t* a, uint32_t b0, uint32_t b1) {
    asm volatile(
        "mma.sync.aligned.m16n8k16.row.col.f32.bf16.bf16.f32 "
        "{%0,%1,%2,%3},{%4,%5,%6,%7},{%8,%9},{%0,%1,%2,%3};\n"
        : "+f"(c[0]), "+f"(c[1]), "+f"(c[2]), "+f"(c[3])
        : "r"(a[0]), "r"(a[1]), "r"(a[2]), "r"(a[3]), "r"(b0), "r"(b1));
}

__device__ __forceinline__ void mma_f16(float* c, const uint32_t* a, uint32_t b0, uint32_t b1) {
    asm volatile(
        "mma.sync.aligned.m16n8k16.row.col.f32.f16.f16.f32 "
        "{%0,%1,%2,%3},{%4,%5,%6,%7},{%8,%9},{%0,%1,%2,%3};\n"
        : "+f"(c[0]), "+f"(c[1]), "+f"(c[2]), "+f"(c[3])
        : "r"(a[0]), "r"(a[1]), "r"(a[2]), "r"(a[3]), "r"(b0), "r"(b1));
}

__device__ __forceinline__ void load_afrag(const uint32_t* __restrict__ g, long rowbase,
                                           int gid, int tig,
                                           uint32_t hi[4][4], uint32_t lo[4][4])
{
    #pragma unroll
    for (int kt = 0; kt < 4; ++kt) {
        long b0 = (rowbase + gid)     * 64 + (kt*8 + tig) * 2;
        long b1 = (rowbase + 8 + gid) * 64 + (kt*8 + tig) * 2;
        uint2 w0 = *(const uint2*)&g[b0];
        uint2 w1 = *(const uint2*)&g[b1];
        uint2 w2 = *(const uint2*)&g[b0 + 8];
        uint2 w3 = *(const uint2*)&g[b1 + 8];
        hi[kt][0] = w0.x; lo[kt][0] = w0.y;
        hi[kt][1] = w1.x; lo[kt][1] = w1.y;
        hi[kt][2] = w2.x; lo[kt][2] = w2.y;
        hi[kt][3] = w3.x; lo[kt][3] = w3.y;
    }
}

__device__ __forceinline__ void score_exp(const uint32_t* sm, int jg, int gid, int tig,
                                          const uint32_t hi[4][4], const uint32_t lo[4][4],
                                          float e0[4], float e1[4])
{
    float s0[4] = {0,0,0,0}, s1[4] = {0,0,0,0};
    #pragma unroll
    for (int kt = 0; kt < 4; ++kt) {
        const uint32_t* p0 = &sm[(jg + gid)     * KSTR + (kt*8 + tig) * 2];
        const uint32_t* p1 = &sm[(jg + 8 + gid) * KSTR + (kt*8 + tig) * 2];
        uint2 b00 = *(const uint2*)p0;
        uint2 b01 = *(const uint2*)(p0 + 8);
        uint2 b10 = *(const uint2*)p1;
        uint2 b11 = *(const uint2*)(p1 + 8);
        mma_bf16(s0, hi[kt], b00.x, b01.x);
        mma_bf16(s1, hi[kt], b10.x, b11.x);
        mma_bf16(s0, lo[kt], b00.x, b01.x);
        mma_bf16(s1, lo[kt], b10.x, b11.x);
        mma_bf16(s0, hi[kt], b00.y, b01.y);
        mma_bf16(s1, hi[kt], b10.y, b11.y);
    }
    #pragma unroll
    for (int u = 0; u < 4; ++u) {
        e0[u] = __expf(s0[u] * 0.125f);
        e1[u] = __expf(s1[u] * 0.125f);
    }
}

// ---- symmetric attn: exp(X X^T/8 - ESH), triangle tiles only ----

__global__ void __launch_bounds__(NTHREADS, 1)
attn_sym_kernel()
{
    extern __shared__ uint32_t smw[];
    uint32_t* aRes[2] = { smw, smw + AR_W };
    uint32_t* bufT[2] = { smw + 2*AR_W, smw + 3*AR_W };
    __half*   etile   = (__half*)(smw + 4*AR_W);
    float*    cps     = (float*)(smw + 4*AR_W + ETILE_W);

    const int tid  = threadIdx.x;
    const int lane = tid & 31, warp = tid >> 5;
    const int gid  = lane >> 2, tig = lane & 3;
    const int rw   = warp >> 2, cw = warp & 3;
    const int bh   = blockIdx.x >> 5;
    const int R    = (blockIdx.x >> 1) & 15;
    const int p    = blockIdx.x & 1;
    const int l0   = R * 128;
    const long rb  = (long)bh * Ls;

    const float4* gA4[2] = { (const float4*)(g_Q + rb * 64),
                             (const float4*)(g_K + rb * 64) };

    #pragma unroll
    for (int m = 0; m < 2; ++m)
        for (int i = tid; i < 2048; i += NTHREADS) {
            int j = i >> 4, q = i & 15;
            ((float4*)aRes[m])[j * (KSTR/4) + q] = gA4[m][(long)(l0 + j) * 16 + q];
        }

    float rp[2][2][2];
    #pragma unroll
    for (int m = 0; m < 2; ++m)
        #pragma unroll
        for (int a = 0; a < 2; ++a) { rp[m][a][0] = 0.f; rp[m][a][1] = 0.f; }

    int ct = ((R & 1) == p) ? R : R + 1;
    float4 pf[2][4];

    #define PREF_T(c) do { \
        _Pragma("unroll") \
        for (int m = 0; m < 2; ++m) \
            _Pragma("unroll") \
            for (int u = 0; u < 4; ++u) \
                pf[m][u] = gA4[m][(long)(c) * 2048 + tid + u*512]; \
    } while (0)

    if (ct < 16) PREF_T(ct);

    for (; ct < 16; ct += 2) {
        __syncthreads();
        #pragma unroll
        for (int m = 0; m < 2; ++m)
            #pragma unroll
            for (int u = 0; u < 4; ++u) {
                int i = tid + u*512; int j = i >> 4, q = i & 15;
                ((float4*)bufT[m])[j * (KSTR/4) + q] = pf[m][u];
            }
        __syncthreads();
        if (ct + 2 < 16) PREF_T(ct + 2);

        const bool diag = (ct == R);

        #pragma unroll 1
        for (int m = 0; m < 2; ++m) {
            float s[2][4][4];
            #pragma unroll
            for (int a = 0; a < 2; ++a)
                #pragma unroll
                for (int n = 0; n < 4; ++n)
                    #pragma unroll
                    for (int u = 0; u < 4; ++u) s[a][n][u] = 0.f;

            #pragma unroll
            for (int kt = 0; kt < 4; ++kt) {
                int w0 = (kt*8 + tig) * 2;
                uint32_t ahi[2][4], alo[2][4];
                #pragma unroll
                for (int rg = 0; rg < 2; ++rg) {
                    int r0 = rw*32 + rg*16 + gid;
                    uint2 x0 = *(const uint2*)&aRes[m][r0     * KSTR + w0];
                    uint2 x1 = *(const uint2*)&aRes[m][(r0+8) * KSTR + w0];
                    uint2 x2 = *(const uint2*)&aRes[m][r0     * KSTR + w0 + 8];
                    uint2 x3 = *(const uint2*)&aRes[m][(r0+8) * KSTR + w0 + 8];
                    ahi[rg][0] = x0.x; alo[rg][0] = x0.y;
                    ahi[rg][1] = x1.x; alo[rg][1] = x1.y;
                    ahi[rg][2] = x2.x; alo[rg][2] = x2.y;
                    ahi[rg][3] = x3.x; alo[rg][3] = x3.y;
                }
                #pragma unroll
                for (int ng = 0; ng < 4; ++ng) {
                    int n = cw*32 + ng*8 + gid;
                    uint2 b0 = *(const uint2*)&bufT[m][n * KSTR + w0];
                    uint2 b1 = *(const uint2*)&bufT[m][n * KSTR + w0 + 8];
                    mma_bf16(s[0][ng], ahi[0], b0.x, b1.x);
                    mma_bf16(s[1][ng], ahi[1], b0.x, b1.x);
                    mma_bf16(s[0][ng], alo[0], b0.x, b1.x);
                    mma_bf16(s[1][ng], alo[1], b0.x, b1.x);
                    mma_bf16(s[0][ng], ahi[0], b0.y, b1.y);
                    mma_bf16(s[1][ng], ahi[1], b0.y, b1.y);
                }
            }

            __half* outE = (m ? g_EKh : g_EQh) + rb * (long)Ls;
            float cp[4][2];
            #pragma unroll
            for (int n = 0; n < 4; ++n) { cp[n][0] = 0.f; cp[n][1] = 0.f; }

            #pragma unroll
            for (int rg = 0; rg < 2; ++rg) {
                #pragma unroll
                for (int ng = 0; ng < 4; ++ng) {
                    // shift by -ESH so fp16 storage cannot overflow on diag entries
                    float e0 = __expf(fmaf(s[rg][ng][0], 0.125f, -ESH));
                    float e1 = __expf(fmaf(s[rg][ng][1], 0.125f, -ESH));
                    float e2 = __expf(fmaf(s[rg][ng][2], 0.125f, -ESH));
                    float e3 = __expf(fmaf(s[rg][ng][3], 0.125f, -ESH));
                    int r0 = l0 + rw*32 + rg*16 + gid;
                    int col = ct*128 + cw*32 + ng*8 + tig*2;
                    *(__half2*)&outE[(long)r0 * Ls + col]     = __floats2half2_rn(e0, e1);
                    *(__half2*)&outE[(long)(r0+8) * Ls + col] = __floats2half2_rn(e2, e3);
                    rp[m][rg][0] += e0 + e1;
                    rp[m][rg][1] += e2 + e3;
                    if (!diag) {
                        int cc = cw*32 + ng*8 + tig*2;
                        int rr = rw*32 + rg*16 + gid;
                        etile[cc*136 + rr]       = __float2half_rn(e0);
                        etile[(cc+1)*136 + rr]   = __float2half_rn(e1);
                        etile[cc*136 + rr + 8]   = __float2half_rn(e2);
                        etile[(cc+1)*136 + rr+8] = __float2half_rn(e3);
                        cp[ng][0] += e0 + e2;
                        cp[ng][1] += e1 + e3;
                    }
                }
            }

            if (!diag) {
                #pragma unroll
                for (int n = 0; n < 4; ++n)
                    #pragma unroll
                    for (int h = 0; h < 2; ++h) {
                        cp[n][h] += __shfl_xor_sync(~0u, cp[n][h], 4);
                        cp[n][h] += __shfl_xor_sync(~0u, cp[n][h], 8);
                        cp[n][h] += __shfl_xor_sync(~0u, cp[n][h], 16);
                    }
                if (gid == 0) {
                    #pragma unroll
                    for (int n = 0; n < 4; ++n) {
                        cps[rw*128 + cw*32 + n*8 + tig*2]     = cp[n][0];
                        cps[rw*128 + cw*32 + n*8 + tig*2 + 1] = cp[n][1];
                    }
                }
            }
            __syncthreads();
            if (!diag) {
                if (tid < 128) {
                    float cv = cps[tid] + cps[128+tid] + cps[256+tid] + cps[384+tid];
                    g_cpart[(((m*BH + bh)*16 + ct)*16 + R)*128 + tid] = cv;
                }
                #pragma unroll
                for (int pass = 0; pass < 4; ++pass) {
                    int i = tid + pass*512;
                    int cc = i >> 4, rc = i & 15;
                    uint4 v = *(const uint4*)&etile[cc*136 + rc*8];
                    *(uint4*)&outE[(long)(ct*128 + cc) * Ls + l0 + rc*8] = v;
                }
            }
            __syncthreads();
        }
    }
    #undef PREF_T

    float* rps = (float*)etile;
    #pragma unroll
    for (int m = 0; m < 2; ++m)
        #pragma unroll
        for (int rg = 0; rg < 2; ++rg)
            #pragma unroll
            for (int h = 0; h < 2; ++h) {
                float v = rp[m][rg][h];
                v += __shfl_xor_sync(~0u, v, 1);
                v += __shfl_xor_sync(~0u, v, 2);
                rp[m][rg][h] = v;
            }
    __syncthreads();
    if (tig == 0) {
        #pragma unroll
        for (int m = 0; m < 2; ++m)
            #pragma unroll
            for (int rg = 0; rg < 2; ++rg)
                #pragma unroll
                for (int h = 0; h < 2; ++h) {
                    int r = rw*32 + rg*16 + h*8 + gid;
                    rps[(m*4 + cw)*128 + r] = rp[m][rg][h];
                }
    }
    __syncthreads();
    if (tid < 256) {
        int m = tid >> 7, r = tid & 127;
        float v = rps[(m*4+0)*128 + r] + rps[(m*4+1)*128 + r]
                + rps[(m*4+2)*128 + r] + rps[(m*4+3)*128 + r];
        g_rpart[(((m*BH + bh)*16 + R)*2 + p)*128 + r] = v;
    }
}

__global__ void __launch_bounds__(128)
rowsum_kernel()
{
    const int bh = blockIdx.x >> 4;
    const int R  = blockIdx.x & 15;
    const int t  = threadIdx.x;
    #pragma unroll
    for (int m = 0; m < 2; ++m) {
        long base = ((long)(m*BH + bh)*16 + R);
        float s = g_rpart[(base*2 + 0)*128 + t] + g_rpart[(base*2 + 1)*128 + t];
        for (int C = 0; C < R; ++C)
            s += g_cpart[(base*16 + C)*128 + t];
        (m ? g_rsK : g_rsQ)[bh * Ls + R*128 + t] = s;
    }
}

__global__ void __launch_bounds__(128)
normalize_add_kernel(float* __restrict__ outAttn)
{
    const int row = blockIdx.x;
    const float invq = 1.0f / g_rsQ[row];
    const float invk = 1.0f / g_rsK[row];
    const uint4* eq = (const uint4*)(g_EQh + (long)row * Ls);
    const uint4* ek = (const uint4*)(g_EKh + (long)row * Ls);
    float4* oa = (float4*)(outAttn + (long)row * Ls);
    #pragma unroll
    for (int u = 0; u < 2; ++u) {
        int i = threadIdx.x + u * 128;
        uint4 a = eq[i], b = ek[i];
        const __half2* ah  = (const __half2*)&a;
        const __half2* bh2 = (const __half2*)&b;
        float2 f0 = __half22float2(ah[0]), f1 = __half22float2(ah[1]);
        float2 f2 = __half22float2(ah[2]), f3 = __half22float2(ah[3]);
        float2 g0 = __half22float2(bh2[0]), g1 = __half22float2(bh2[1]);
        float2 g2 = __half22float2(bh2[2]), g3 = __half22float2(bh2[3]);
        float4 o0, o1;
        o0.x = f0.x*invq + g0.x*invk;  o0.y = f0.y*invq + g0.y*invk;
        o0.z = f1.x*invq + g1.x*invk;  o0.w = f1.y*invq + g1.y*invk;
        o1.x = f2.x*invq + g2.x*invk;  o1.y = f2.y*invq + g2.y*invk;
        o1.z = f3.x*invq + g3.x*invk;  o1.w = f3.y*invq + g3.y*invk;
        oa[i*2]     = o0;
        oa[i*2 + 1] = o1;
    }
}

__global__ void __launch_bounds__(NTHREADS, 1)
sdpa_flash_kernel(float* __restrict__ outO)
{
    extern __shared__ uint32_t smw[];
    uint32_t* bufK   = smw;
    uint32_t* bufV   = smw + 128 * KSTR;
    float*    redsum = (float*)(smw + SDPA_TILEW);
    float*    sinv   = redsum + 256;
    float*    redO   = (float*)smw;

    const int tid  = threadIdx.x;
    const int lane = tid & 31, warp = tid >> 5;
    const int gid  = lane >> 2, tig = lane & 3;
    const int rg   = warp >> 3;
    const int cg   = warp & 7;
    const int jg   = cg * 16;
    const int jp0  = cg * 8;
    const int bh   = blockIdx.x >> 6;
    const int l0   = (blockIdx.x & 63) * BROWS;
    const long rb  = (long)bh * Ls;

    uint32_t qhi[4][4], qlo[4][4];
    load_afrag(g_Q, rb + l0 + rg * 16, gid, tig, qhi, qlo);

    float oacc[8][4];
    #pragma unroll
    for (int dg = 0; dg < 8; ++dg)
        #pragma unroll
        for (int u = 0; u < 4; ++u) oacc[dg][u] = 0.f;
    float s0sum = 0.f, s1sum = 0.f;

    float4* smK4 = (float4*)bufK;
    float4* smV4 = (float4*)bufV;
    const float4* gK4 = (const float4*)(g_K + rb * 64);
    const float4* gV4 = (const float4*)(g_VT + (long)bh * Dh * 2048);

    float4 pk[4], pv[4];
    #define PREF_KV(ct) do { \
        const float4* ak = gK4 + (ct) * 2048; \
        const float4* av = gV4 + (ct) * 32; \
        _Pragma("unroll") \
        for (int u = 0; u < 4; ++u) { int i = tid + u*512; pk[u] = ak[i]; \
            int d = i >> 5, q = i & 31; pv[u] = av[(long)d * 512 + q]; } \
    } while (0)
    #define STORE_KV() do { \
        _Pragma("unroll") \
        for (int u = 0; u < 4; ++u) { int i = tid + u*512; int j = i >> 4, q = i & 15; \
            smK4[j * (KSTR/4) + q] = pk[u]; \
            int d = i >> 5, q2 = i & 31; smV4[d * (VSTR/4) + q2] = pv[u]; } \
    } while (0)

    PREF_KV(0);
    #pragma unroll 1
    for (int ct = 0; ct < NTILES; ++ct) {
        __syncthreads();
        STORE_KV();
        __syncthreads();
        if (ct + 1 < NTILES) PREF_KV(ct + 1);

        float e0[4], e1[4];
        score_exp(bufK, jg, gid, tig, qhi, qlo, e0, e1);
        s0sum += e0[0] + e0[1] + e1[0] + e1[1];
        s1sum += e0[2] + e0[3] + e1[2] + e1[3];

        uint32_t pa[4];
        { __half2 h;
          h = __floats2half2_rn(e0[0], e0[1]); pa[0] = *(uint32_t*)&h;
          h = __floats2half2_rn(e0[2], e0[3]); pa[1] = *(uint32_t*)&h;
          h = __floats2half2_rn(e1[0], e1[1]); pa[2] = *(uint32_t*)&h;
          h = __floats2half2_rn(e1[2], e1[3]); pa[3] = *(uint32_t*)&h; }

        #pragma unroll
        for (int dg = 0; dg < 8; ++dg) {
            const uint32_t* pp = &bufV[(dg*8 + gid) * VSTR + (jp0 + tig) * 2];
            uint2 w0 = *(const uint2*)pp;
            uint2 w1 = *(const uint2*)(pp + 8);
            mma_f16(oacc[dg], pa, w0.x, w1.x);
            mma_f16(oacc[dg], pa, w0.y, w1.y);
        }
    }
    #undef PREF_KV
    #undef STORE_KV

    s0sum += __shfl_xor_sync(~0u, s0sum, 1); s0sum += __shfl_xor_sync(~0u, s0sum, 2);
    s1sum += __shfl_xor_sync(~0u, s1sum, 1); s1sum += __shfl_xor_sync(~0u, s1sum, 2);
    __syncthreads();
    if (tig == 0) {
        redsum[warp*16 + gid]     = s0sum;
        redsum[warp*16 + 8 + gid] = s1sum;
    }
    __syncthreads();
    if (tid < BROWS) {
        int rgi = tid >> 4, lr = tid & 15;
        float t = 0.f;
        #pragma unroll
        for (int c = 0; c < 8; ++c) t += redsum[(rgi*8 + c)*16 + lr];
        sinv[tid] = 1.0f / t;
    }
    __syncthreads();
    #pragma unroll
    for (int dg = 0; dg < 8; ++dg) {
        float* r = redO + warp * 1024;
        int d = dg*8 + tig*2;
        r[gid*64 + d]           = oacc[dg][0];
        r[gid*64 + d + 1]       = oacc[dg][1];
        r[(gid+8)*64 + d]       = oacc[dg][2];
        r[(gid+8)*64 + d + 1]   = oacc[dg][3];
    }
    __syncthreads();

    float* ob = outO + (rb + l0) * Dh;
    for (int i = tid; i < BROWS * Dh; i += NTHREADS) {
        int r = i >> 6;
        int rgi = r >> 4, lr = r & 15, d = i & 63;
        float v = 0.f;
        #pragma unroll
        for (int c = 0; c < 8; ++c) v += redO[(rgi*8 + c)*1024 + lr*64 + d];
        ob[i] = v * sinv[r];
    }
}

extern "C" void kernel_launch(void* const* d_in, const int* in_sizes, int n_in,
                              void* d_out, int out_size)
{
    const float* q = (const float*)d_in[0];
    const float* k = (const float*)d_in[1];
    const float* v = (const float*)d_in[2];

    float* outO    = (float*)d_out;
    float* outAttn = (float*)d_out + 2097152;

    cudaFuncSetAttribute(attn_sym_kernel,
                         cudaFuncAttributeMaxDynamicSharedMemorySize, ATTN_SMEM_BYTES);
    cudaFuncSetAttribute(sdpa_flash_kernel,
                         cudaFuncAttributeMaxDynamicSharedMemorySize, SDPA_SMEM_BYTES);

    convert_qk_kernel<<<(2 * BH * Ls * 32) / 256, 256>>>(q, k);
    convert_v_kernel<<<BH * 16, 256>>>(v);
    attn_sym_kernel<<<BH * 32, NTHREADS, ATTN_SMEM_BYTES>>>();
    rowsum_kernel<<<BH * 16, 128>>>();
    normalize_add_kernel<<<BH * Ls, 128>>>(outAttn);
    sdpa_flash_kernel<<<1024, NTHREADS, SDPA_SMEM_BYTES>>>(outO);
}

// round 10
// speedup vs baseline: 1.5417x; 1.5417x over previous
#include <cuda_runtime.h>
#include <cuda_bf16.h>
#include <cuda_fp16.h>
#include <cstdint>

// B=2,H=8 -> BH=16 heads; L=S=2048; D=64; fp32 in/out.
#define BH        16
#define Ls        2048
#define Dh        64
#define NT        128
#define NTILES    16
#define BROWS     32
#define NTHREADS  512
#define KSTR      72
#define VSTR      136

#define SDPA_TILEW      (128*KSTR + 64*VSTR)
#define SDPA_SMEM_BYTES ((SDPA_TILEW + 256 + 32) * 4)

#define ATTN_TILEW       (128*KSTR)
#define ATTN_SMEM_BYTES  ((4*ATTN_TILEW + 512 + 16) * 4)   // 149568

// Exponent shift: stored values are exp(s/8 - ESH); cancels in normalization.
// Keeps fp16 finite on QQ^T/KK^T diagonal (score/8 up to ~16 -> e^8 = 2981).
#define ESH 8.0f

// Packed interleaved hi/lo (bf16 Q/K rows, fp16 V^T).
__device__ uint32_t g_Q [BH * Ls * 64];
__device__ uint32_t g_K [BH * Ls * 64];
__device__ uint32_t g_VT[BH * Dh * 2048];
// Unnormalized shifted exp scratch (fp16) + row sums.
__device__ __half g_EQh[(long)BH * Ls * Ls];
__device__ __half g_EKh[(long)BH * Ls * Ls];
__device__ float g_rsQ[BH * Ls];
__device__ float g_rsK[BH * Ls];

// ---------------- converts ----------------

__global__ void convert_qk_kernel(const float* __restrict__ Q, const float* __restrict__ K)
{
    const unsigned NPAIR = BH * Ls * 32;
    unsigned i = blockIdx.x * 256 + threadIdx.x;
    const float2* src = (i < NPAIR) ? (const float2*)Q : (const float2*)K;
    uint32_t*     dst = (i < NPAIR) ? g_Q : g_K;
    unsigned p = (i < NPAIR) ? i : i - NPAIR;
    float2 v = src[p];
    __nv_bfloat16 hx = __float2bfloat16(v.x), hy = __float2bfloat16(v.y);
    __nv_bfloat162 hh; hh.x = hx; hh.y = hy;
    __nv_bfloat162 ll = __floats2bfloat162_rn(v.x - __bfloat162float(hx),
                                              v.y - __bfloat162float(hy));
    dst[2u*p]     = *reinterpret_cast<uint32_t*>(&hh);
    dst[2u*p + 1] = *reinterpret_cast<uint32_t*>(&ll);
}

__global__ void convert_v_kernel(const float* __restrict__ V)
{
    __shared__ float st[128][65];
    const int bh = blockIdx.x >> 4;
    const int j0 = (blockIdx.x & 15) * 128;
    const int tid = threadIdx.x;
    const float* vb = V + ((long)bh * Ls + j0) * Dh;
    for (int i = tid; i < 128 * 64; i += 256)
        st[i >> 6][i & 63] = vb[i];
    __syncthreads();
    for (int i = tid; i < 64 * 64; i += 256) {
        int d = i >> 6, jp = i & 63;
        float v0 = st[jp*2][d], v1 = st[jp*2 + 1][d];
        __half h0 = __float2half_rn(v0), h1 = __float2half_rn(v1);
        __half2 hh; hh.x = h0; hh.y = h1;
        __half2 ll; ll.x = __float2half_rn(v0 - __half2float(h0));
                    ll.y = __float2half_rn(v1 - __half2float(h1));
        long w = ((long)(bh * Dh + d) * 1024 + (j0 >> 1) + jp) * 2;
        g_VT[w]     = *reinterpret_cast<uint32_t*>(&hh);
        g_VT[w + 1] = *reinterpret_cast<uint32_t*>(&ll);
    }
}

// ---------------- mma helpers ----------------

__device__ __forceinline__ void mma_bf16(float* c, const uint32_t* a, uint32_t b0, uint32_t b1) {
    asm volatile(
        "mma.sync.aligned.m16n8k16.row.col.f32.bf16.bf16.f32 "
        "{%0,%1,%2,%3},{%4,%5,%6,%7},{%8,%9},{%0,%1,%2,%3};\n"
        : "+f"(c[0]), "+f"(c[1]), "+f"(c[2]), "+f"(c[3])
        : "r"(a[0]), "r"(a[1]), "r"(a[2]), "r"(a[3]), "r"(b0), "r"(b1));
}

__device__ __forceinline__ void mma_f16(float* c, const uint32_t* a, uint32_t b0, uint32_t b1) {
    asm volatile(
        "mma.sync.aligned.m16n8k16.row.col.f32.f16.f16.f32 "
        "{%0,%1,%2,%3},{%4,%5,%6,%7},{%8,%9},{%0,%1,%2,%3};\n"
        : "+f"(c[0]), "+f"(c[1]), "+f"(c[2]), "+f"(c[3])
        : "r"(a[0]), "r"(a[1]), "r"(a[2]), "r"(a[3]), "r"(b0), "r"(b1));
}

__device__ __forceinline__ void load_afrag(const uint32_t* __restrict__ g, long rowbase,
                                           int gid, int tig,
                                           uint32_t hi[4][4], uint32_t lo[4][4])
{
    #pragma unroll
    for (int kt = 0; kt < 4; ++kt) {
        long b0 = (rowbase + gid)     * 64 + (kt*8 + tig) * 2;
        long b1 = (rowbase + 8 + gid) * 64 + (kt*8 + tig) * 2;
        uint2 w0 = *(const uint2*)&g[b0];
        uint2 w1 = *(const uint2*)&g[b1];
        uint2 w2 = *(const uint2*)&g[b0 + 8];
        uint2 w3 = *(const uint2*)&g[b1 + 8];
        hi[kt][0] = w0.x; lo[kt][0] = w0.y;
        hi[kt][1] = w1.x; lo[kt][1] = w1.y;
        hi[kt][2] = w2.x; lo[kt][2] = w2.y;
        hi[kt][3] = w3.x; lo[kt][3] = w3.y;
    }
}

// 16-row x 16-col score tile, e = exp(s/8) (sdpa; no shift).
__device__ __forceinline__ void score_exp(const uint32_t* sm, int jg, int gid, int tig,
                                          const uint32_t hi[4][4], const uint32_t lo[4][4],
                                          float e0[4], float e1[4])
{
    float s0[4] = {0,0,0,0}, s1[4] = {0,0,0,0};
    #pragma unroll
    for (int kt = 0; kt < 4; ++kt) {
        const uint32_t* p0 = &sm[(jg + gid)     * KSTR + (kt*8 + tig) * 2];
        const uint32_t* p1 = &sm[(jg + 8 + gid) * KSTR + (kt*8 + tig) * 2];
        uint2 b00 = *(const uint2*)p0;
        uint2 b01 = *(const uint2*)(p0 + 8);
        uint2 b10 = *(const uint2*)p1;
        uint2 b11 = *(const uint2*)(p1 + 8);
        mma_bf16(s0, hi[kt], b00.x, b01.x);
        mma_bf16(s1, hi[kt], b10.x, b11.x);
        mma_bf16(s0, lo[kt], b00.x, b01.x);
        mma_bf16(s1, lo[kt], b10.x, b11.x);
        mma_bf16(s0, hi[kt], b00.y, b01.y);
        mma_bf16(s1, hi[kt], b10.y, b11.y);
    }
    #pragma unroll
    for (int u = 0; u < 4; ++u) {
        e0[u] = __expf(s0[u] * 0.125f);
        e1[u] = __expf(s1[u] * 0.125f);
    }
}

// 32-row x 16-col score tile, e = exp(s/8 - ESH) (attn; shifted for fp16 storage).
__device__ __forceinline__ void score_exp32(const uint32_t* sm, int jg, int gid, int tig,
                                            const uint32_t hi[2][4][4],
                                            const uint32_t lo[2][4][4],
                                            float e[2][2][4])
{
    float s[2][2][4];
    #pragma unroll
    for (int rg = 0; rg < 2; ++rg)
        #pragma unroll
        for (int ng = 0; ng < 2; ++ng)
            #pragma unroll
            for (int u = 0; u < 4; ++u) s[rg][ng][u] = 0.f;

    #pragma unroll
    for (int kt = 0; kt < 4; ++kt) {
        const uint32_t* p0 = &sm[(jg + gid)     * KSTR + (kt*8 + tig) * 2];
        const uint32_t* p1 = &sm[(jg + 8 + gid) * KSTR + (kt*8 + tig) * 2];
        uint2 b00 = *(const uint2*)p0;
        uint2 b01 = *(const uint2*)(p0 + 8);
        uint2 b10 = *(const uint2*)p1;
        uint2 b11 = *(const uint2*)(p1 + 8);
        mma_bf16(s[0][0], hi[0][kt], b00.x, b01.x);
        mma_bf16(s[0][1], hi[0][kt], b10.x, b11.x);
        mma_bf16(s[1][0], hi[1][kt], b00.x, b01.x);
        mma_bf16(s[1][1], hi[1][kt], b10.x, b11.x);
        mma_bf16(s[0][0], lo[0][kt], b00.x, b01.x);
        mma_bf16(s[0][1], lo[0][kt], b10.x, b11.x);
        mma_bf16(s[1][0], lo[1][kt], b00.x, b01.x);
        mma_bf16(s[1][1], lo[1][kt], b10.x, b11.x);
        mma_bf16(s[0][0], hi[0][kt], b00.y, b01.y);
        mma_bf16(s[0][1], hi[0][kt], b10.y, b11.y);
        mma_bf16(s[1][0], hi[1][kt], b00.y, b01.y);
        mma_bf16(s[1][1], hi[1][kt], b10.y, b11.y);
    }
    #pragma unroll
    for (int rg = 0; rg < 2; ++rg)
        #pragma unroll
        for (int ng = 0; ng < 2; ++ng)
            #pragma unroll
            for (int u = 0; u < 4; ++u)
                e[rg][ng][u] = __expf(fmaf(s[rg][ng][u], 0.125f, -ESH));
}

// ---------------- cp.async helpers ----------------

__device__ __forceinline__ void cpasync16(uint32_t smaddr, const void* gptr) {
    asm volatile("cp.async.cg.shared.global [%0], [%1], 16;\n"
                 :: "r"(smaddr), "l"(gptr));
}
#define CP_COMMIT()  asm volatile("cp.async.commit_group;\n" ::: "memory")
#define CP_WAIT(N)   asm volatile("cp.async.wait_group %0;\n" :: "n"(N) : "memory")

// ---------------- attn pass: shifted exp scores (fp16) + row sums ----------------
// warps 0-7: exp(QQ^T/8 - 8) -> g_EQh ; warps 8-15: exp(KK^T/8 - 8) -> g_EKh.
// Each warp 32 rows x 16 cols per tile; double-buffered cp.async staging.

__global__ void __launch_bounds__(NTHREADS, 1)
attn_exp_kernel()
{
    extern __shared__ uint32_t smw[];
    uint32_t* bufQ[2] = { smw,                 smw + 2*ATTN_TILEW };
    uint32_t* bufK[2] = { smw + ATTN_TILEW,    smw + 3*ATTN_TILEW };
    float* red = (float*)(smw + 4*ATTN_TILEW);   // [2 mats][8 cg][32 rows]

    const int tid  = threadIdx.x;
    const int lane = tid & 31, warp = tid >> 5;
    const int gid  = lane >> 2, tig = lane & 3;
    const int mat  = warp >> 3;          // 0=Q, 1=K
    const int cg   = warp & 7;
    const int jg   = cg * 16;
    const int bh   = blockIdx.x >> 6;
    const int l0   = (blockIdx.x & 63) * BROWS;
    const long rb  = (long)bh * Ls;

    uint32_t ahi[2][4][4], alo[2][4][4];
    {
        const uint32_t* gA = mat ? g_K : g_Q;
        load_afrag(gA, rb + l0,      gid, tig, ahi[0], alo[0]);
        load_afrag(gA, rb + l0 + 16, gid, tig, ahi[1], alo[1]);
    }

    const float4* gQ4 = (const float4*)(g_Q + rb * 64);
    const float4* gK4 = (const float4*)(g_K + rb * 64);
    uint32_t smQ[2], smK[2];
    smQ[0] = (uint32_t)__cvta_generic_to_shared(bufQ[0]);
    smQ[1] = (uint32_t)__cvta_generic_to_shared(bufQ[1]);
    smK[0] = (uint32_t)__cvta_generic_to_shared(bufK[0]);
    smK[1] = (uint32_t)__cvta_generic_to_shared(bufK[1]);

    #define ISSUE_TILE(ct, s) do { \
        const float4* aq = gQ4 + (ct) * 2048; \
        const float4* ak = gK4 + (ct) * 2048; \
        _Pragma("unroll") \
        for (int u = 0; u < 4; ++u) { \
            int i = tid + u*512; int j = i >> 4, qq = i & 15; \
            uint32_t off = (uint32_t)(j * (KSTR/4) + qq) * 16u; \
            cpasync16(smQ[s] + off, aq + i); \
            cpasync16(smK[s] + off, ak + i); \
        } \
        CP_COMMIT(); \
    } while (0)

    __half* ob = (mat ? g_EKh : g_EQh) + (rb + l0) * (long)Ls;

    float ssum[2][2] = {{0.f,0.f},{0.f,0.f}};

    ISSUE_TILE(0, 0);
    #pragma unroll 1
    for (int ct = 0; ct < NTILES; ++ct) {
        const int s = ct & 1;
        if (ct + 1 < NTILES) { ISSUE_TILE(ct + 1, s ^ 1); CP_WAIT(1); }
        else                 { CP_WAIT(0); }
        __syncthreads();

        const uint32_t* mybuf = mat ? bufK[s] : bufQ[s];
        float e[2][2][4];
        score_exp32(mybuf, jg, gid, tig, ahi, alo, e);

        int c0 = ct * NT + jg + tig * 2;
        #pragma unroll
        for (int rg = 0; rg < 2; ++rg) {
            ssum[rg][0] += e[rg][0][0] + e[rg][0][1] + e[rg][1][0] + e[rg][1][1];
            ssum[rg][1] += e[rg][0][2] + e[rg][0][3] + e[rg][1][2] + e[rg][1][3];
            __half* r0 = ob + (long)(rg*16 + gid)     * Ls + c0;
            __half* r1 = ob + (long)(rg*16 + gid + 8) * Ls + c0;
            *(__half2*)r0       = __floats2half2_rn(e[rg][0][0], e[rg][0][1]);
            *(__half2*)(r0 + 8) = __floats2half2_rn(e[rg][1][0], e[rg][1][1]);
            *(__half2*)r1       = __floats2half2_rn(e[rg][0][2], e[rg][0][3]);
            *(__half2*)(r1 + 8) = __floats2half2_rn(e[rg][1][2], e[rg][1][3]);
        }
        __syncthreads();
    }
    #undef ISSUE_TILE

    #pragma unroll
    for (int rg = 0; rg < 2; ++rg)
        #pragma unroll
        for (int h = 0; h < 2; ++h) {
            ssum[rg][h] += __shfl_xor_sync(~0u, ssum[rg][h], 1);
            ssum[rg][h] += __shfl_xor_sync(~0u, ssum[rg][h], 2);
        }
    if (tig == 0) {
        red[mat*256 + cg*32 + gid]      = ssum[0][0];
        red[mat*256 + cg*32 + 8 + gid]  = ssum[0][1];
        red[mat*256 + cg*32 + 16 + gid] = ssum[1][0];
        red[mat*256 + cg*32 + 24 + gid] = ssum[1][1];
    }
    __syncthreads();
    if (tid < 64) {
        int m = tid >> 5, r = tid & 31;
        float t = 0.f;
        #pragma unroll
        for (int c = 0; c < 8; ++c) t += red[m*256 + c*32 + r];
        (m ? g_rsK : g_rsQ)[bh * Ls + l0 + r] = t;
    }
}

// ---------------- normalize + add: out = EQ/sq + EK/sk ----------------

__global__ void __launch_bounds__(128)
normalize_add_kernel(float* __restrict__ outAttn)
{
    const int row = blockIdx.x;
    const float invq = 1.0f / g_rsQ[row];
    const float invk = 1.0f / g_rsK[row];
    const uint4* eq = (const uint4*)(g_EQh + (long)row * Ls);
    const uint4* ek = (const uint4*)(g_EKh + (long)row * Ls);
    float4* oa = (float4*)(outAttn + (long)row * Ls);
    #pragma unroll
    for (int u = 0; u < 2; ++u) {
        int i = threadIdx.x + u * 128;
        uint4 a = eq[i], b = ek[i];
        const __half2* ah  = (const __half2*)&a;
        const __half2* bh2 = (const __half2*)&b;
        float2 f0 = __half22float2(ah[0]), f1 = __half22float2(ah[1]);
        float2 f2 = __half22float2(ah[2]), f3 = __half22float2(ah[3]);
        float2 g0 = __half22float2(bh2[0]), g1 = __half22float2(bh2[1]);
        float2 g2 = __half22float2(bh2[2]), g3 = __half22float2(bh2[3]);
        float4 o0, o1;
        o0.x = f0.x*invq + g0.x*invk;  o0.y = f0.y*invq + g0.y*invk;
        o0.z = f1.x*invq + g1.x*invk;  o0.w = f1.y*invq + g1.y*invk;
        o1.x = f2.x*invq + g2.x*invk;  o1.y = f2.y*invq + g2.y*invk;
        o1.z = f3.x*invq + g3.x*invk;  o1.w = f3.y*invq + g3.y*invk;
        oa[i*2]     = o0;
        oa[i*2 + 1] = o1;
    }
}

// ---------------- flash-style sdpa (round-6, unchanged) ----------------

__global__ void __launch_bounds__(NTHREADS, 1)
sdpa_flash_kernel(float* __restrict__ outO)
{
    extern __shared__ uint32_t smw[];
    uint32_t* bufK   = smw;
    uint32_t* bufV   = smw + 128 * KSTR;
    float*    redsum = (float*)(smw + SDPA_TILEW);
    float*    sinv   = redsum + 256;
    float*    redO   = (float*)smw;

    const int tid  = threadIdx.x;
    const int lane = tid & 31, warp = tid >> 5;
    const int gid  = lane >> 2, tig = lane & 3;
    const int rg   = warp >> 3;
    const int cg   = warp & 7;
    const int jg   = cg * 16;
    const int jp0  = cg * 8;
    const int bh   = blockIdx.x >> 6;
    const int l0   = (blockIdx.x & 63) * BROWS;
    const long rb  = (long)bh * Ls;

    uint32_t qhi[4][4], qlo[4][4];
    load_afrag(g_Q, rb + l0 + rg * 16, gid, tig, qhi, qlo);

    float oacc[8][4];
    #pragma unroll
    for (int dg = 0; dg < 8; ++dg)
        #pragma unroll
        for (int u = 0; u < 4; ++u) oacc[dg][u] = 0.f;
    float s0sum = 0.f, s1sum = 0.f;

    float4* smK4 = (float4*)bufK;
    float4* smV4 = (float4*)bufV;
    const float4* gK4 = (const float4*)(g_K + rb * 64);
    const float4* gV4 = (const float4*)(g_VT + (long)bh * Dh * 2048);

    float4 pk[4], pv[4];
    #define PREF_KV(ct) do { \
        const float4* ak = gK4 + (ct) * 2048; \
        const float4* av = gV4 + (ct) * 32; \
        _Pragma("unroll") \
        for (int u = 0; u < 4; ++u) { int i = tid + u*512; pk[u] = ak[i]; \
            int d = i >> 5, q = i & 31; pv[u] = av[(long)d * 512 + q]; } \
    } while (0)
    #define STORE_KV() do { \
        _Pragma("unroll") \
        for (int u = 0; u < 4; ++u) { int i = tid + u*512; int j = i >> 4, q = i & 15; \
            smK4[j * (KSTR/4) + q] = pk[u]; \
            int d = i >> 5, q2 = i & 31; smV4[d * (VSTR/4) + q2] = pv[u]; } \
    } while (0)

    PREF_KV(0);
    #pragma unroll 1
    for (int ct = 0; ct < NTILES; ++ct) {
        __syncthreads();
        STORE_KV();
        __syncthreads();
        if (ct + 1 < NTILES) PREF_KV(ct + 1);

        float e0[4], e1[4];
        score_exp(bufK, jg, gid, tig, qhi, qlo, e0, e1);
        s0sum += e0[0] + e0[1] + e1[0] + e1[1];
        s1sum += e0[2] + e0[3] + e1[2] + e1[3];

        uint32_t pa[4];
        { __half2 h;
          h = __floats2half2_rn(e0[0], e0[1]); pa[0] = *(uint32_t*)&h;
          h = __floats2half2_rn(e0[2], e0[3]); pa[1] = *(uint32_t*)&h;
          h = __floats2half2_rn(e1[0], e1[1]); pa[2] = *(uint32_t*)&h;
          h = __floats2half2_rn(e1[2], e1[3]); pa[3] = *(uint32_t*)&h; }

        #pragma unroll
        for (int dg = 0; dg < 8; ++dg) {
            const uint32_t* pp = &bufV[(dg*8 + gid) * VSTR + (jp0 + tig) * 2];
            uint2 w0 = *(const uint2*)pp;
            uint2 w1 = *(const uint2*)(pp + 8);
            mma_f16(oacc[dg], pa, w0.x, w1.x);
            mma_f16(oacc[dg], pa, w0.y, w1.y);
        }
    }
    #undef PREF_KV
    #undef STORE_KV

    s0sum += __shfl_xor_sync(~0u, s0sum, 1); s0sum += __shfl_xor_sync(~0u, s0sum, 2);
    s1sum += __shfl_xor_sync(~0u, s1sum, 1); s1sum += __shfl_xor_sync(~0u, s1sum, 2);
    __syncthreads();
    if (tig == 0) {
        redsum[warp*16 + gid]     = s0sum;
        redsum[warp*16 + 8 + gid] = s1sum;
    }
    __syncthreads();
    if (tid < BROWS) {
        int rgi = tid >> 4, lr = tid & 15;
        float t = 0.f;
        #pragma unroll
        for (int c = 0; c < 8; ++c) t += redsum[(rgi*8 + c)*16 + lr];
        sinv[tid] = 1.0f / t;
    }
    __syncthreads();
    #pragma unroll
    for (int dg = 0; dg < 8; ++dg) {
        float* r = redO + warp * 1024;
        int d = dg*8 + tig*2;
        r[gid*64 + d]           = oacc[dg][0];
        r[gid*64 + d + 1]       = oacc[dg][1];
        r[(gid+8)*64 + d]       = oacc[dg][2];
        r[(gid+8)*64 + d + 1]   = oacc[dg][3];
    }
    __syncthreads();

    float* ob = outO + (rb + l0) * Dh;
    for (int i = tid; i < BROWS * Dh; i += NTHREADS) {
        int r = i >> 6;
        int rgi = r >> 4, lr = r & 15, d = i & 63;
        float v = 0.f;
        #pragma unroll
        for (int c = 0; c < 8; ++c) v += redO[(rgi*8 + c)*1024 + lr*64 + d];
        ob[i] = v * sinv[r];
    }
}

// ---------------- launch ----------------

extern "C" void kernel_launch(void* const* d_in, const int* in_sizes, int n_in,
                              void* d_out, int out_size)
{
    const float* q = (const float*)d_in[0];
    const float* k = (const float*)d_in[1];
    const float* v = (const float*)d_in[2];

    float* outO    = (float*)d_out;             // [2,8,2048,64]
    float* outAttn = (float*)d_out + 2097152;   // [2,8,2048,2048]

    cudaFuncSetAttribute(attn_exp_kernel,
                         cudaFuncAttributeMaxDynamicSharedMemorySize, ATTN_SMEM_BYTES);
    cudaFuncSetAttribute(sdpa_flash_kernel,
                         cudaFuncAttributeMaxDynamicSharedMemorySize, SDPA_SMEM_BYTES);

    convert_qk_kernel<<<(2 * BH * Ls * 32) / 256, 256>>>(q, k);
    convert_v_kernel<<<BH * 16, 256>>>(v);
    attn_exp_kernel<<<1024, NTHREADS, ATTN_SMEM_BYTES>>>();
    normalize_add_kernel<<<BH * Ls, 128>>>(outAttn);
    sdpa_flash_kernel<<<1024, NTHREADS, SDPA_SMEM_BYTES>>>(outO);
}

// round 11
// speedup vs baseline: 1.5429x; 1.0008x over previous
#include <cuda_runtime.h>
#include <cuda_bf16.h>
#include <cuda_fp16.h>
#include <cstdint>

// B=2,H=8 -> BH=16 heads; L=S=2048; D=64; fp32 in/out.
#define BH        16
#define Ls        2048
#define Dh        64
#define NT        128
#define NTILES    16
#define BROWS     32
#define NTHREADS  512
#define KSTR      72
#define VSTR      136

#define SDPA_TILEW      (128*KSTR + 64*VSTR)
#define SDPA_SMEM_BYTES ((SDPA_TILEW + 256 + 32) * 4)

#define ATTN_TILEW       (128*KSTR)
#define ATTN_SMEM_BYTES  ((4*ATTN_TILEW + 512 + 16) * 4)   // 149568

// Exponent shift: stored values are exp(s/8 - ESH); cancels in normalization.
// Keeps fp16 finite on QQ^T/KK^T diagonal (score/8 up to ~16 -> e^8 = 2981).
#define ESH 8.0f

// Packed interleaved hi/lo (bf16 Q/K rows, fp16 V^T).
__device__ uint32_t g_Q [BH * Ls * 64];
__device__ uint32_t g_K [BH * Ls * 64];
__device__ uint32_t g_VT[BH * Dh * 2048];
// Unnormalized shifted exp scratch (fp16) + row sums.
__device__ __half g_EQh[(long)BH * Ls * Ls];
__device__ __half g_EKh[(long)BH * Ls * Ls];
__device__ float g_rsQ[BH * Ls];
__device__ float g_rsK[BH * Ls];

// ---------------- converts ----------------

__global__ void convert_qk_kernel(const float* __restrict__ Q, const float* __restrict__ K)
{
    const unsigned NPAIR = BH * Ls * 32;
    unsigned i = blockIdx.x * 256 + threadIdx.x;
    const float2* src = (i < NPAIR) ? (const float2*)Q : (const float2*)K;
    uint32_t*     dst = (i < NPAIR) ? g_Q : g_K;
    unsigned p = (i < NPAIR) ? i : i - NPAIR;
    float2 v = src[p];
    __nv_bfloat16 hx = __float2bfloat16(v.x), hy = __float2bfloat16(v.y);
    __nv_bfloat162 hh; hh.x = hx; hh.y = hy;
    __nv_bfloat162 ll = __floats2bfloat162_rn(v.x - __bfloat162float(hx),
                                              v.y - __bfloat162float(hy));
    dst[2u*p]     = *reinterpret_cast<uint32_t*>(&hh);
    dst[2u*p + 1] = *reinterpret_cast<uint32_t*>(&ll);
}

__global__ void convert_v_kernel(const float* __restrict__ V)
{
    __shared__ float st[128][65];
    const int bh = blockIdx.x >> 4;
    const int j0 = (blockIdx.x & 15) * 128;
    const int tid = threadIdx.x;
    const float* vb = V + ((long)bh * Ls + j0) * Dh;
    for (int i = tid; i < 128 * 64; i += 256)
        st[i >> 6][i & 63] = vb[i];
    __syncthreads();
    for (int i = tid; i < 64 * 64; i += 256) {
        int d = i >> 6, jp = i & 63;
        float v0 = st[jp*2][d], v1 = st[jp*2 + 1][d];
        __half h0 = __float2half_rn(v0), h1 = __float2half_rn(v1);
        __half2 hh; hh.x = h0; hh.y = h1;
        __half2 ll; ll.x = __float2half_rn(v0 - __half2float(h0));
                    ll.y = __float2half_rn(v1 - __half2float(h1));
        long w = ((long)(bh * Dh + d) * 1024 + (j0 >> 1) + jp) * 2;
        g_VT[w]     = *reinterpret_cast<uint32_t*>(&hh);
        g_VT[w + 1] = *reinterpret_cast<uint32_t*>(&ll);
    }
}

// ---------------- mma helpers ----------------

__device__ __forceinline__ void mma_bf16(float* c, const uint32_t* a, uint32_t b0, uint32_t b1) {
    asm volatile(
        "mma.sync.aligned.m16n8k16.row.col.f32.bf16.bf16.f32 "
        "{%0,%1,%2,%3},{%4,%5,%6,%7},{%8,%9},{%0,%1,%2,%3};\n"
        : "+f"(c[0]), "+f"(c[1]), "+f"(c[2]), "+f"(c[3])
        : "r"(a[0]), "r"(a[1]), "r"(a[2]), "r"(a[3]), "r"(b0), "r"(b1));
}

__device__ __forceinline__ void mma_f16(float* c, const uint32_t* a, uint32_t b0, uint32_t b1) {
    asm volatile(
        "mma.sync.aligned.m16n8k16.row.col.f32.f16.f16.f32 "
        "{%0,%1,%2,%3},{%4,%5,%6,%7},{%8,%9},{%0,%1,%2,%3};\n"
        : "+f"(c[0]), "+f"(c[1]), "+f"(c[2]), "+f"(c[3])
        : "r"(a[0]), "r"(a[1]), "r"(a[2]), "r"(a[3]), "r"(b0), "r"(b1));
}

__device__ __forceinline__ void load_afrag(const uint32_t* __restrict__ g, long rowbase,
                                           int gid, int tig,
                                           uint32_t hi[4][4], uint32_t lo[4][4])
{
    #pragma unroll
    for (int kt = 0; kt < 4; ++kt) {
        long b0 = (rowbase + gid)     * 64 + (kt*8 + tig) * 2;
        long b1 = (rowbase + 8 + gid) * 64 + (kt*8 + tig) * 2;
        uint2 w0 = *(const uint2*)&g[b0];
        uint2 w1 = *(const uint2*)&g[b1];
        uint2 w2 = *(const uint2*)&g[b0 + 8];
        uint2 w3 = *(const uint2*)&g[b1 + 8];
        hi[kt][0] = w0.x; lo[kt][0] = w0.y;
        hi[kt][1] = w1.x; lo[kt][1] = w1.y;
        hi[kt][2] = w2.x; lo[kt][2] = w2.y;
        hi[kt][3] = w3.x; lo[kt][3] = w3.y;
    }
}

// 16-row x 16-col score tile, e = exp(s/8) (sdpa; no shift).
__device__ __forceinline__ void score_exp(const uint32_t* sm, int jg, int gid, int tig,
                                          const uint32_t hi[4][4], const uint32_t lo[4][4],
                                          float e0[4], float e1[4])
{
    float s0[4] = {0,0,0,0}, s1[4] = {0,0,0,0};
    #pragma unroll
    for (int kt = 0; kt < 4; ++kt) {
        const uint32_t* p0 = &sm[(jg + gid)     * KSTR + (kt*8 + tig) * 2];
        const uint32_t* p1 = &sm[(jg + 8 + gid) * KSTR + (kt*8 + tig) * 2];
        uint2 b00 = *(const uint2*)p0;
        uint2 b01 = *(const uint2*)(p0 + 8);
        uint2 b10 = *(const uint2*)p1;
        uint2 b11 = *(const uint2*)(p1 + 8);
        mma_bf16(s0, hi[kt], b00.x, b01.x);
        mma_bf16(s1, hi[kt], b10.x, b11.x);
        mma_bf16(s0, lo[kt], b00.x, b01.x);
        mma_bf16(s1, lo[kt], b10.x, b11.x);
        mma_bf16(s0, hi[kt], b00.y, b01.y);
        mma_bf16(s1, hi[kt], b10.y, b11.y);
    }
    #pragma unroll
    for (int u = 0; u < 4; ++u) {
        e0[u] = __expf(s0[u] * 0.125f);
        e1[u] = __expf(s1[u] * 0.125f);
    }
}

// 32-row x 16-col score tile, e = exp(s/8 - ESH) (attn; shifted for fp16 storage).
__device__ __forceinline__ void score_exp32(const uint32_t* sm, int jg, int gid, int tig,
                                            const uint32_t hi[2][4][4],
                                            const uint32_t lo[2][4][4],
                                            float e[2][2][4])
{
    float s[2][2][4];
    #pragma unroll
    for (int rg = 0; rg < 2; ++rg)
        #pragma unroll
        for (int ng = 0; ng < 2; ++ng)
            #pragma unroll
            for (int u = 0; u < 4; ++u) s[rg][ng][u] = 0.f;

    #pragma unroll
    for (int kt = 0; kt < 4; ++kt) {
        const uint32_t* p0 = &sm[(jg + gid)     * KSTR + (kt*8 + tig) * 2];
        const uint32_t* p1 = &sm[(jg + 8 + gid) * KSTR + (kt*8 + tig) * 2];
        uint2 b00 = *(const uint2*)p0;
        uint2 b01 = *(const uint2*)(p0 + 8);
        uint2 b10 = *(const uint2*)p1;
        uint2 b11 = *(const uint2*)(p1 + 8);
        mma_bf16(s[0][0], hi[0][kt], b00.x, b01.x);
        mma_bf16(s[0][1], hi[0][kt], b10.x, b11.x);
        mma_bf16(s[1][0], hi[1][kt], b00.x, b01.x);
        mma_bf16(s[1][1], hi[1][kt], b10.x, b11.x);
        mma_bf16(s[0][0], lo[0][kt], b00.x, b01.x);
        mma_bf16(s[0][1], lo[0][kt], b10.x, b11.x);
        mma_bf16(s[1][0], lo[1][kt], b00.x, b01.x);
        mma_bf16(s[1][1], lo[1][kt], b10.x, b11.x);
        mma_bf16(s[0][0], hi[0][kt], b00.y, b01.y);
        mma_bf16(s[0][1], hi[0][kt], b10.y, b11.y);
        mma_bf16(s[1][0], hi[1][kt], b00.y, b01.y);
        mma_bf16(s[1][1], hi[1][kt], b10.y, b11.y);
    }
    #pragma unroll
    for (int rg = 0; rg < 2; ++rg)
        #pragma unroll
        for (int ng = 0; ng < 2; ++ng)
            #pragma unroll
            for (int u = 0; u < 4; ++u)
                e[rg][ng][u] = __expf(fmaf(s[rg][ng][u], 0.125f, -ESH));
}

// ---------------- cp.async helpers ----------------

__device__ __forceinline__ void cpasync16(uint32_t smaddr, const void* gptr) {
    asm volatile("cp.async.cg.shared.global [%0], [%1], 16;\n"
                 :: "r"(smaddr), "l"(gptr));
}
#define CP_COMMIT()  asm volatile("cp.async.commit_group;\n" ::: "memory")
#define CP_WAIT(N)   asm volatile("cp.async.wait_group %0;\n" :: "n"(N) : "memory")

// ---------------- attn pass: shifted exp scores (fp16) + row sums ----------------

__global__ void __launch_bounds__(NTHREADS, 1)
attn_exp_kernel()
{
    extern __shared__ uint32_t smw[];
    uint32_t* bufQ[2] = { smw,                 smw + 2*ATTN_TILEW };
    uint32_t* bufK[2] = { smw + ATTN_TILEW,    smw + 3*ATTN_TILEW };
    float* red = (float*)(smw + 4*ATTN_TILEW);   // [2 mats][8 cg][32 rows]

    const int tid  = threadIdx.x;
    const int lane = tid & 31, warp = tid >> 5;
    const int gid  = lane >> 2, tig = lane & 3;
    const int mat  = warp >> 3;          // 0=Q, 1=K
    const int cg   = warp & 7;
    const int jg   = cg * 16;
    const int bh   = blockIdx.x >> 6;
    const int l0   = (blockIdx.x & 63) * BROWS;
    const long rb  = (long)bh * Ls;

    uint32_t ahi[2][4][4], alo[2][4][4];
    {
        const uint32_t* gA = mat ? g_K : g_Q;
        load_afrag(gA, rb + l0,      gid, tig, ahi[0], alo[0]);
        load_afrag(gA, rb + l0 + 16, gid, tig, ahi[1], alo[1]);
    }

    const float4* gQ4 = (const float4*)(g_Q + rb * 64);
    const float4* gK4 = (const float4*)(g_K + rb * 64);
    uint32_t smQ[2], smK[2];
    smQ[0] = (uint32_t)__cvta_generic_to_shared(bufQ[0]);
    smQ[1] = (uint32_t)__cvta_generic_to_shared(bufQ[1]);
    smK[0] = (uint32_t)__cvta_generic_to_shared(bufK[0]);
    smK[1] = (uint32_t)__cvta_generic_to_shared(bufK[1]);

    #define ISSUE_TILE(ct, s) do { \
        const float4* aq = gQ4 + (ct) * 2048; \
        const float4* ak = gK4 + (ct) * 2048; \
        _Pragma("unroll") \
        for (int u = 0; u < 4; ++u) { \
            int i = tid + u*512; int j = i >> 4, qq = i & 15; \
            uint32_t off = (uint32_t)(j * (KSTR/4) + qq) * 16u; \
            cpasync16(smQ[s] + off, aq + i); \
            cpasync16(smK[s] + off, ak + i); \
        } \
        CP_COMMIT(); \
    } while (0)

    __half* ob = (mat ? g_EKh : g_EQh) + (rb + l0) * (long)Ls;

    float ssum[2][2] = {{0.f,0.f},{0.f,0.f}};

    ISSUE_TILE(0, 0);
    #pragma unroll 1
    for (int ct = 0; ct < NTILES; ++ct) {
        const int s = ct & 1;
        if (ct + 1 < NTILES) { ISSUE_TILE(ct + 1, s ^ 1); CP_WAIT(1); }
        else                 { CP_WAIT(0); }
        __syncthreads();

        const uint32_t* mybuf = mat ? bufK[s] : bufQ[s];
        float e[2][2][4];
        score_exp32(mybuf, jg, gid, tig, ahi, alo, e);

        int c0 = ct * NT + jg + tig * 2;
        #pragma unroll
        for (int rg = 0; rg < 2; ++rg) {
            ssum[rg][0] += e[rg][0][0] + e[rg][0][1] + e[rg][1][0] + e[rg][1][1];
            ssum[rg][1] += e[rg][0][2] + e[rg][0][3] + e[rg][1][2] + e[rg][1][3];
            __half* r0 = ob + (long)(rg*16 + gid)     * Ls + c0;
            __half* r1 = ob + (long)(rg*16 + gid + 8) * Ls + c0;
            *(__half2*)r0       = __floats2half2_rn(e[rg][0][0], e[rg][0][1]);
            *(__half2*)(r0 + 8) = __floats2half2_rn(e[rg][1][0], e[rg][1][1]);
            *(__half2*)r1       = __floats2half2_rn(e[rg][0][2], e[rg][0][3]);
            *(__half2*)(r1 + 8) = __floats2half2_rn(e[rg][1][2], e[rg][1][3]);
        }
        __syncthreads();
    }
    #undef ISSUE_TILE

    #pragma unroll
    for (int rg = 0; rg < 2; ++rg)
        #pragma unroll
        for (int h = 0; h < 2; ++h) {
            ssum[rg][h] += __shfl_xor_sync(~0u, ssum[rg][h], 1);
            ssum[rg][h] += __shfl_xor_sync(~0u, ssum[rg][h], 2);
        }
    if (tig == 0) {
        red[mat*256 + cg*32 + gid]      = ssum[0][0];
        red[mat*256 + cg*32 + 8 + gid]  = ssum[0][1];
        red[mat*256 + cg*32 + 16 + gid] = ssum[1][0];
        red[mat*256 + cg*32 + 24 + gid] = ssum[1][1];
    }
    __syncthreads();
    if (tid < 64) {
        int m = tid >> 5, r = tid & 31;
        float t = 0.f;
        #pragma unroll
        for (int c = 0; c < 8; ++c) t += red[m*256 + c*32 + r];
        (m ? g_rsK : g_rsQ)[bh * Ls + l0 + r] = t;
    }
}

// ---------------- normalize + add: out = EQ/sq + EK/sk ----------------

__global__ void __launch_bounds__(128)
normalize_add_kernel(float* __restrict__ outAttn)
{
    const int row = blockIdx.x;
    const float invq = 1.0f / g_rsQ[row];
    const float invk = 1.0f / g_rsK[row];
    const uint4* eq = (const uint4*)(g_EQh + (long)row * Ls);
    const uint4* ek = (const uint4*)(g_EKh + (long)row * Ls);
    float4* oa = (float4*)(outAttn + (long)row * Ls);
    #pragma unroll
    for (int u = 0; u < 2; ++u) {
        int i = threadIdx.x + u * 128;
        uint4 a = eq[i], b = ek[i];
        const __half2* ah  = (const __half2*)&a;
        const __half2* bh2 = (const __half2*)&b;
        float2 f0 = __half22float2(ah[0]), f1 = __half22float2(ah[1]);
        float2 f2 = __half22float2(ah[2]), f3 = __half22float2(ah[3]);
        float2 g0 = __half22float2(bh2[0]), g1 = __half22float2(bh2[1]);
        float2 g2 = __half22float2(bh2[2]), g3 = __half22float2(bh2[3]);
        float4 o0, o1;
        o0.x = f0.x*invq + g0.x*invk;  o0.y = f0.y*invq + g0.y*invk;
        o0.z = f1.x*invq + g1.x*invk;  o0.w = f1.y*invq + g1.y*invk;
        o1.x = f2.x*invq + g2.x*invk;  o1.y = f2.y*invq + g2.y*invk;
        o1.z = f3.x*invq + g3.x*invk;  o1.w = f3.y*invq + g3.y*invk;
        oa[i*2]     = o0;
        oa[i*2 + 1] = o1;
    }
}

// ---------------- flash-style sdpa (unchanged) ----------------

__global__ void __launch_bounds__(NTHREADS, 1)
sdpa_flash_kernel(float* __restrict__ outO)
{
    extern __shared__ uint32_t smw[];
    uint32_t* bufK   = smw;
    uint32_t* bufV   = smw + 128 * KSTR;
    float*    redsum = (float*)(smw + SDPA_TILEW);
    float*    sinv   = redsum + 256;
    float*    redO   = (float*)smw;

    const int tid  = threadIdx.x;
    const int lane = tid & 31, warp = tid >> 5;
    const int gid  = lane >> 2, tig = lane & 3;
    const int rg   = warp >> 3;
    const int cg   = warp & 7;
    const int jg   = cg * 16;
    const int jp0  = cg * 8;
    const int bh   = blockIdx.x >> 6;
    const int l0   = (blockIdx.x & 63) * BROWS;
    const long rb  = (long)bh * Ls;

    uint32_t qhi[4][4], qlo[4][4];
    load_afrag(g_Q, rb + l0 + rg * 16, gid, tig, qhi, qlo);

    float oacc[8][4];
    #pragma unroll
    for (int dg = 0; dg < 8; ++dg)
        #pragma unroll
        for (int u = 0; u < 4; ++u) oacc[dg][u] = 0.f;
    float s0sum = 0.f, s1sum = 0.f;

    float4* smK4 = (float4*)bufK;
    float4* smV4 = (float4*)bufV;
    const float4* gK4 = (const float4*)(g_K + rb * 64);
    const float4* gV4 = (const float4*)(g_VT + (long)bh * Dh * 2048);

    float4 pk[4], pv[4];
    #define PREF_KV(ct) do { \
        const float4* ak = gK4 + (ct) * 2048; \
        const float4* av = gV4 + (ct) * 32; \
        _Pragma("unroll") \
        for (int u = 0; u < 4; ++u) { int i = tid + u*512; pk[u] = ak[i]; \
            int d = i >> 5, q = i & 31; pv[u] = av[(long)d * 512 + q]; } \
    } while (0)
    #define STORE_KV() do { \
        _Pragma("unroll") \
        for (int u = 0; u < 4; ++u) { int i = tid + u*512; int j = i >> 4, q = i & 15; \
            smK4[j * (KSTR/4) + q] = pk[u]; \
            int d = i >> 5, q2 = i & 31; smV4[d * (VSTR/4) + q2] = pv[u]; } \
    } while (0)

    PREF_KV(0);
    #pragma unroll 1
    for (int ct = 0; ct < NTILES; ++ct) {
        __syncthreads();
        STORE_KV();
        __syncthreads();
        if (ct + 1 < NTILES) PREF_KV(ct + 1);

        float e0[4], e1[4];
        score_exp(bufK, jg, gid, tig, qhi, qlo, e0, e1);
        s0sum += e0[0] + e0[1] + e1[0] + e1[1];
        s1sum += e0[2] + e0[3] + e1[2] + e1[3];

        uint32_t pa[4];
        { __half2 h;
          h = __floats2half2_rn(e0[0], e0[1]); pa[0] = *(uint32_t*)&h;
          h = __floats2half2_rn(e0[2], e0[3]); pa[1] = *(uint32_t*)&h;
          h = __floats2half2_rn(e1[0], e1[1]); pa[2] = *(uint32_t*)&h;
          h = __floats2half2_rn(e1[2], e1[3]); pa[3] = *(uint32_t*)&h; }

        #pragma unroll
        for (int dg = 0; dg < 8; ++dg) {
            const uint32_t* pp = &bufV[(dg*8 + gid) * VSTR + (jp0 + tig) * 2];
            uint2 w0 = *(const uint2*)pp;
            uint2 w1 = *(const uint2*)(pp + 8);
            mma_f16(oacc[dg], pa, w0.x, w1.x);
            mma_f16(oacc[dg], pa, w0.y, w1.y);
        }
    }
    #undef PREF_KV
    #undef STORE_KV

    s0sum += __shfl_xor_sync(~0u, s0sum, 1); s0sum += __shfl_xor_sync(~0u, s0sum, 2);
    s1sum += __shfl_xor_sync(~0u, s1sum, 1); s1sum += __shfl_xor_sync(~0u, s1sum, 2);
    __syncthreads();
    if (tig == 0) {
        redsum[warp*16 + gid]     = s0sum;
        redsum[warp*16 + 8 + gid] = s1sum;
    }
    __syncthreads();
    if (tid < BROWS) {
        int rgi = tid >> 4, lr = tid & 15;
        float t = 0.f;
        #pragma unroll
        for (int c = 0; c < 8; ++c) t += redsum[(rgi*8 + c)*16 + lr];
        sinv[tid] = 1.0f / t;
    }
    __syncthreads();
    #pragma unroll
    for (int dg = 0; dg < 8; ++dg) {
        float* r = redO + warp * 1024;
        int d = dg*8 + tig*2;
        r[gid*64 + d]           = oacc[dg][0];
        r[gid*64 + d + 1]       = oacc[dg][1];
        r[(gid+8)*64 + d]       = oacc[dg][2];
        r[(gid+8)*64 + d + 1]   = oacc[dg][3];
    }
    __syncthreads();

    float* ob = outO + (rb + l0) * Dh;
    for (int i = tid; i < BROWS * Dh; i += NTHREADS) {
        int r = i >> 6;
        int rgi = r >> 4, lr = r & 15, d = i & 63;
        float v = 0.f;
        #pragma unroll
        for (int c = 0; c < 8; ++c) v += redO[(rgi*8 + c)*1024 + lr*64 + d];
        ob[i] = v * sinv[r];
    }
}

// ---------------- launch: fork sdpa onto the per-thread built-in stream ----------------
// Dependency chains after converts are independent:
//   main stream:        attn_exp -> normalize_add   (tensor/L1 then DRAM-bound)
//   per-thread stream:  sdpa_flash                  (tensor/L1-bound)
// Fork/join via events (no stream creation -> no device-side pool allocation).
// If this TU's default stream IS the per-thread stream, everything lands on one
// stream and the sequence degrades to the previous (correct) serial order.

extern "C" void kernel_launch(void* const* d_in, const int* in_sizes, int n_in,
                              void* d_out, int out_size)
{
    const float* q = (const float*)d_in[0];
    const float* k = (const float*)d_in[1];
    const float* v = (const float*)d_in[2];

    float* outO    = (float*)d_out;             // [2,8,2048,64]
    float* outAttn = (float*)d_out + 2097152;   // [2,8,2048,2048]

    cudaFuncSetAttribute(attn_exp_kernel,
                         cudaFuncAttributeMaxDynamicSharedMemorySize, ATTN_SMEM_BYTES);
    cudaFuncSetAttribute(sdpa_flash_kernel,
                         cudaFuncAttributeMaxDynamicSharedMemorySize, SDPA_SMEM_BYTES);

    cudaEvent_t evFork, evJoin;
    cudaEventCreateWithFlags(&evFork, cudaEventDisableTiming);
    cudaEventCreateWithFlags(&evJoin, cudaEventDisableTiming);

    convert_qk_kernel<<<(2 * BH * Ls * 32) / 256, 256>>>(q, k);
    convert_v_kernel<<<BH * 16, 256>>>(v);

    // fork: sdpa on the per-thread default stream after converts
    cudaEventRecord(evFork, 0);
    cudaStreamWaitEvent(cudaStreamPerThread, evFork, 0);
    sdpa_flash_kernel<<<1024, NTHREADS, SDPA_SMEM_BYTES, cudaStreamPerThread>>>(outO);
    cudaEventRecord(evJoin, cudaStreamPerThread);

    // main chain
    attn_exp_kernel<<<1024, NTHREADS, ATTN_SMEM_BYTES>>>();
    normalize_add_kernel<<<BH * Ls, 128>>>(outAttn);

    // join: main stream waits for sdpa before kernel_launch's work is "done"
    cudaStreamWaitEvent(0, evJoin, 0);
}